// round 6
// baseline (speedup 1.0000x reference)
#include <cuda_runtime.h>
#include <cuda_fp16.h>
#include <cstdint>

// Problem constants (from reference)
#define NU 100000
#define NI 50000
#define NN 150000           // NU + NI
#define DIM 64
#define NE 3000000
#define DELTA 0.5f

#define SCAN_CHUNK 1024
#define N_CHUNKS ((NN + SCAN_CHUNK - 1) / SCAN_CHUNK)   // 147

#define EDGE_BLOCKS ((NE + 255) / 256)                  // 11719
#define PULL_BLOCKS ((NN * 16 + 255) / 256)             // 9375
#define NODE2_BLOCKS ((2 * NN + 255) / 256)

// ---------------------------------------------------------------------------
// __device__ global scratch. Modality m uses slot [m].
// ---------------------------------------------------------------------------
__device__ __half g_h1[2][(size_t)NN * DIM];
__device__ __half g_h2[2][(size_t)NN * DIM];
__device__ int    g_deg[2 * NN];
__device__ int    g_off[2 * NN];
__device__ int    g_rank[2 * NE];
__device__ int    g_partials[2 * N_CHUNKS];
__device__ int    g_scanned[2 * N_CHUNKS];
__device__ uint2  g_sw[2][(size_t)NE];

// ---------------------------------------------------------------------------
// step 1 — zero both degree arrays
// ---------------------------------------------------------------------------
__global__ void zero_deg_kernel(int* __restrict__ deg) {
    int i = blockIdx.x * blockDim.x + threadIdx.x;
    if (i < 2 * NN) deg[i] = 0;
}

// step 2 — fused histogram; atomicAdd return value = within-bucket rank
__global__ void __launch_bounds__(256)
hist_kernel(const int* __restrict__ dst0, const int* __restrict__ dst1,
            int* __restrict__ deg, int* __restrict__ rank) {
    int b = blockIdx.x;
    int m = (b >= EDGE_BLOCKS) ? 1 : 0;
    int e = (b - m * EDGE_BLOCKS) * 256 + threadIdx.x;
    if (e >= NE) return;
    const int* dst = m ? dst1 : dst0;
    int d = __ldg(dst + e);
    rank[m * NE + e] = atomicAdd(deg + m * NN + d, 1);
}

// step 3a — per-chunk exclusive scan, fused over both modalities
__global__ void __launch_bounds__(SCAN_CHUNK)
scan1_kernel(const int* __restrict__ deg, int* __restrict__ off,
             int* __restrict__ partials) {
    __shared__ int sm[2][SCAN_CHUNK];
    int b = blockIdx.x;
    int m = (b >= N_CHUNKS) ? 1 : 0;
    int chunk = b - m * N_CHUNKS;
    int t = threadIdx.x;
    int li = chunk * SCAN_CHUNK + t;
    int v = (li < NN) ? deg[m * NN + li] : 0;
    sm[0][t] = v;
    __syncthreads();
    int cur = 0;
    #pragma unroll
    for (int ofs = 1; ofs < SCAN_CHUNK; ofs <<= 1) {
        int nxt = cur ^ 1;
        int val = sm[cur][t];
        if (t >= ofs) val += sm[cur][t - ofs];
        sm[nxt][t] = val;
        __syncthreads();
        cur = nxt;
    }
    int inclusive = sm[cur][t];
    if (li < NN) off[m * NN + li] = inclusive - v;
    if (t == SCAN_CHUNK - 1) partials[m * N_CHUNKS + chunk] = inclusive;
}

// step 3b — parallel scan of chunk totals; grid=2
__global__ void __launch_bounds__(256)
scan2_kernel(const int* __restrict__ partials, int* __restrict__ scanned) {
    __shared__ int sm[2][256];
    int m = blockIdx.x;
    int t = threadIdx.x;
    int v = (t < N_CHUNKS) ? partials[m * N_CHUNKS + t] : 0;
    sm[0][t] = v;
    __syncthreads();
    int cur = 0;
    #pragma unroll
    for (int ofs = 1; ofs < 256; ofs <<= 1) {
        int nxt = cur ^ 1;
        int val = sm[cur][t];
        if (t >= ofs) val += sm[cur][t - ofs];
        sm[nxt][t] = val;
        __syncthreads();
        cur = nxt;
    }
    if (t < N_CHUNKS) scanned[m * N_CHUNKS + t] = sm[cur][t] - v;  // exclusive
}

// step 3c — add chunk bases
__global__ void scan3_kernel(int* __restrict__ off,
                             const int* __restrict__ scanned) {
    int i = blockIdx.x * blockDim.x + threadIdx.x;
    if (i >= 2 * NN) return;
    int m = (i >= NN) ? 1 : 0;
    int li = i - m * NN;
    off[i] += scanned[m * N_CHUNKS + li / SCAN_CHUNK];
}

// step 4 — atomic-free scatter: pos = off[dst] + rank
__global__ void __launch_bounds__(256)
sort_scatter_kernel(const int* __restrict__ src0, const int* __restrict__ dst0,
                    const float* __restrict__ w0,
                    const int* __restrict__ src1, const int* __restrict__ dst1,
                    const float* __restrict__ w1,
                    const int* __restrict__ off, const int* __restrict__ rank,
                    uint2* __restrict__ sw) {
    int b = blockIdx.x;
    int m = (b >= EDGE_BLOCKS) ? 1 : 0;
    int e = (b - m * EDGE_BLOCKS) * 256 + threadIdx.x;
    if (e >= NE) return;
    const int* src = m ? src1 : src0;
    const int* dst = m ? dst1 : dst0;
    const float* w = m ? w1 : w0;
    int d = __ldg(dst + e);
    int pos = __ldg(off + m * NN + d) + __ldg(rank + m * NE + e);
    sw[(size_t)m * NE + pos] =
        make_uint2((unsigned)__ldg(src + e), __float_as_uint(__ldg(w + e)));
}

// ---------------------------------------------------------------------------
// Fused pull kernel, fp32 accumulation, BATCH-4 edge processing:
// per batch, 4 independent sw loads issue together, then 4 independent
// gathers — raises per-warp MLP from ~2 to ~4-8 to cover L2/DRAM latency
// (the round-5 measurement showed pulls are latency-bound, not BW-bound).
//   IN_F16 = false : layer 1, reads fp32 pref/repre (split at NU)
//   IN_F16 = true  : reads fp16 feature buffer
//   TO_OUT = true  : layer 3, writes fp32 d_out in concat layout (col m*64)
// ---------------------------------------------------------------------------
template<bool IN_F16, bool TO_OUT>
__global__ void __launch_bounds__(256)
pull_kernel(const uint2* __restrict__ swBase,
            const int* __restrict__ offBase, const int* __restrict__ degBase,
            const float4* __restrict__ fA0, const float4* __restrict__ fB0,
            const float4* __restrict__ fA1, const float4* __restrict__ fB1,
            const uint2* __restrict__ hIn0, const uint2* __restrict__ hIn1,
            uint2* __restrict__ hOut0, uint2* __restrict__ hOut1,
            float* __restrict__ fout) {
    int b = blockIdx.x;
    int m = (b >= PULL_BLOCKS) ? 1 : 0;
    int t = (b - m * PULL_BLOCKS) * 256 + threadIdx.x;
    int node = t >> 4;
    int j = t & 15;
    if (node >= NN) return;

    const uint2* sw = swBase + (size_t)m * NE;
    const int* off = offBase + m * NN;
    const int* deg = degBase + m * NN;
    const float4* fA = m ? fA1 : fA0;
    const float4* fB = m ? fB1 : fB0;
    const uint2* hIn = m ? hIn1 : hIn0;

    auto gather = [&](int s) -> float4 {
        if (IN_F16) {
            uint2 v = __ldg(hIn + (size_t)s * 16 + j);
            __half2 a = *reinterpret_cast<__half2*>(&v.x);
            __half2 c = *reinterpret_cast<__half2*>(&v.y);
            float2 fa = __half22float2(a);
            float2 fc = __half22float2(c);
            return make_float4(fa.x, fa.y, fc.x, fc.y);
        } else {
            return (s < NU) ? __ldg(fA + (size_t)s * 16 + j)
                            : __ldg(fB + (size_t)(s - NU) * 16 + j);
        }
    };

    // residual term (same buffer as gathers)
    float4 acc = gather(node);
    acc.x *= DELTA; acc.y *= DELTA; acc.z *= DELTA; acc.w *= DELTA;
    float4 acc2 = make_float4(0.f, 0.f, 0.f, 0.f);

    const int o = __ldg(off + node);
    const int n = __ldg(deg + node);
    const int end = o + n;

    int k = o;
    // batch-4: 4 sw loads issue back-to-back, then 4 independent gathers
    for (; k + 4 <= end; k += 4) {
        uint2 e0 = __ldg(sw + k);
        uint2 e1 = __ldg(sw + k + 1);
        uint2 e2 = __ldg(sw + k + 2);
        uint2 e3 = __ldg(sw + k + 3);
        float4 v0 = gather((int)e0.x);
        float4 v1 = gather((int)e1.x);
        float4 v2 = gather((int)e2.x);
        float4 v3 = gather((int)e3.x);
        float w0 = __uint_as_float(e0.y);
        float w1 = __uint_as_float(e1.y);
        float w2 = __uint_as_float(e2.y);
        float w3 = __uint_as_float(e3.y);
        acc.x  = fmaf(w0, v0.x, acc.x);
        acc.y  = fmaf(w0, v0.y, acc.y);
        acc.z  = fmaf(w0, v0.z, acc.z);
        acc.w  = fmaf(w0, v0.w, acc.w);
        acc2.x = fmaf(w1, v1.x, acc2.x);
        acc2.y = fmaf(w1, v1.y, acc2.y);
        acc2.z = fmaf(w1, v1.z, acc2.z);
        acc2.w = fmaf(w1, v1.w, acc2.w);
        acc.x  = fmaf(w2, v2.x, acc.x);
        acc.y  = fmaf(w2, v2.y, acc.y);
        acc.z  = fmaf(w2, v2.z, acc.z);
        acc.w  = fmaf(w2, v2.w, acc.w);
        acc2.x = fmaf(w3, v3.x, acc2.x);
        acc2.y = fmaf(w3, v3.y, acc2.y);
        acc2.z = fmaf(w3, v3.z, acc2.z);
        acc2.w = fmaf(w3, v3.w, acc2.w);
    }
    // tail (0-3 edges)
    for (; k < end; k++) {
        uint2 e0 = __ldg(sw + k);
        float4 v0 = gather((int)e0.x);
        float w0 = __uint_as_float(e0.y);
        acc.x = fmaf(w0, v0.x, acc.x);
        acc.y = fmaf(w0, v0.y, acc.y);
        acc.z = fmaf(w0, v0.z, acc.z);
        acc.w = fmaf(w0, v0.w, acc.w);
    }
    acc.x += acc2.x; acc.y += acc2.y; acc.z += acc2.z; acc.w += acc2.w;

    if (TO_OUT) {
        int halfOff = m * 64;
        size_t base = (node < NU)
            ? (size_t)node * 128 + halfOff
            : (size_t)NU * 128 + (size_t)(node - NU) * 128 + halfOff;
        *reinterpret_cast<float4*>(fout + base + (size_t)j * 4) = acc;
    } else {
        uint2* hOut = m ? hOut1 : hOut0;
        __half2 ha = __floats2half2_rn(acc.x, acc.y);
        __half2 hb = __floats2half2_rn(acc.z, acc.w);
        uint2 ov;
        ov.x = *reinterpret_cast<unsigned*>(&ha);
        ov.y = *reinterpret_cast<unsigned*>(&hb);
        hOut[(size_t)node * 16 + j] = ov;
    }
}

// ---------------------------------------------------------------------------
// Orchestration: 9 launches total.
// ---------------------------------------------------------------------------
extern "C" void kernel_launch(void* const* d_in, const int* in_sizes, int n_in,
                              void* d_out, int out_size) {
    const int*   ei_img   = (const int*)  d_in[0];
    const float* ew_img   = (const float*)d_in[1];
    const int*   ei_txt   = (const int*)  d_in[2];
    const float* ew_txt   = (const float*)d_in[3];
    const float* img_pref = (const float*)d_in[4];
    const float* txt_pref = (const float*)d_in[5];
    const float* img_repr = (const float*)d_in[6];
    const float* txt_repr = (const float*)d_in[7];
    float* out = (float*)d_out;

    const int* src0 = ei_img;        const int* dst0 = ei_img + NE;
    const int* src1 = ei_txt;        const int* dst1 = ei_txt + NE;

    __half *h1_0, *h2_0;
    int *deg, *off, *rank, *partials, *scanned;
    uint2* sw;
    cudaGetSymbolAddress((void**)&h1_0, g_h1);
    cudaGetSymbolAddress((void**)&h2_0, g_h2);
    cudaGetSymbolAddress((void**)&deg, g_deg);
    cudaGetSymbolAddress((void**)&off, g_off);
    cudaGetSymbolAddress((void**)&rank, g_rank);
    cudaGetSymbolAddress((void**)&partials, g_partials);
    cudaGetSymbolAddress((void**)&scanned, g_scanned);
    cudaGetSymbolAddress((void**)&sw, g_sw);
    uint2* h1u0 = reinterpret_cast<uint2*>(h1_0);
    uint2* h1u1 = reinterpret_cast<uint2*>(h1_0 + (size_t)NN * DIM);
    uint2* h2u0 = reinterpret_cast<uint2*>(h2_0);
    uint2* h2u1 = reinterpret_cast<uint2*>(h2_0 + (size_t)NN * DIM);

    // Build both CSCs
    zero_deg_kernel<<<NODE2_BLOCKS, 256>>>(deg);
    hist_kernel<<<2 * EDGE_BLOCKS, 256>>>(dst0, dst1, deg, rank);
    scan1_kernel<<<2 * N_CHUNKS, SCAN_CHUNK>>>(deg, off, partials);
    scan2_kernel<<<2, 256>>>(partials, scanned);
    scan3_kernel<<<NODE2_BLOCKS, 256>>>(off, scanned);
    sort_scatter_kernel<<<2 * EDGE_BLOCKS, 256>>>(
        src0, dst0, ew_img, src1, dst1, ew_txt, off, rank, sw);

    // Layer 1: fp32 pref/repre -> fp16 buf1
    pull_kernel<false, false><<<2 * PULL_BLOCKS, 256>>>(
        sw, off, deg,
        reinterpret_cast<const float4*>(img_pref),
        reinterpret_cast<const float4*>(img_repr),
        reinterpret_cast<const float4*>(txt_pref),
        reinterpret_cast<const float4*>(txt_repr),
        nullptr, nullptr,
        h1u0, h1u1, nullptr);
    // Layer 2: fp16 buf1 -> fp16 buf2
    pull_kernel<true, false><<<2 * PULL_BLOCKS, 256>>>(
        sw, off, deg,
        nullptr, nullptr, nullptr, nullptr,
        h1u0, h1u1,
        h2u0, h2u1, nullptr);
    // Layer 3: fp16 buf2 -> fp32 d_out (concat layout)
    pull_kernel<true, true><<<2 * PULL_BLOCKS, 256>>>(
        sw, off, deg,
        nullptr, nullptr, nullptr, nullptr,
        h2u0, h2u1,
        nullptr, nullptr, out);
}

// round 9
// speedup vs baseline: 1.1893x; 1.1893x over previous
#include <cuda_runtime.h>
#include <cuda_fp16.h>
#include <cstdint>

// Problem constants (from reference)
#define NU 100000
#define NI 50000
#define NN 150000           // NU + NI
#define DIM 64
#define NE 3000000
#define DELTA 0.5f

#define SCAN_CHUNK 1024
#define N_CHUNKS ((NN + SCAN_CHUNK - 1) / SCAN_CHUNK)   // 147

#define EDGE_BLOCKS ((NE + 255) / 256)                  // 11719
#define PULL8_BLOCKS ((NN * 8 + 255) / 256)             // 4688
#define NODE2_BLOCKS ((2 * NN + 255) / 256)
#define CVT_BLOCKS ((2 * NN * 8 + 255) / 256)           // 9375

// ---------------------------------------------------------------------------
// __device__ global scratch. Feature buffers are declared as uint4 so the
// 16-byte alignment required by LDG.128/STG.128 is guaranteed by the type
// (a __half declaration only guarantees 2-byte alignment — UB that is the
// prime suspect for the round-7/8 container crashes).
// Row layout: node row = 8 uint4 = 64 fp16 features.
// ---------------------------------------------------------------------------
__device__ uint4  g_hA[2][(size_t)NN * 8];
__device__ uint4  g_hB[2][(size_t)NN * 8];
__device__ int    g_deg[2 * NN];
__device__ int    g_off[2 * NN];
__device__ int    g_rank[2 * NE];
__device__ int    g_partials[2 * N_CHUNKS];
__device__ int    g_scanned[2 * N_CHUNKS];
__device__ uint2  g_sw[2][(size_t)NE];

// ---------------------------------------------------------------------------
// Convert fp32 inputs -> fp16 ego buffers (both modalities, one launch).
// Thread = one uint4 (8 features = 2 input float4s).
// ---------------------------------------------------------------------------
__global__ void __launch_bounds__(256)
convert_kernel(const float4* __restrict__ p0, const float4* __restrict__ r0,
               const float4* __restrict__ p1, const float4* __restrict__ r1,
               uint4* __restrict__ h0, uint4* __restrict__ h1) {
    int i = blockIdx.x * blockDim.x + threadIdx.x;
    if (i >= 2 * NN * 8) return;
    int m = (i >= NN * 8) ? 1 : 0;
    int li = i - m * NN * 8;          // node*8 + j
    int node = li >> 3;
    const float4* pref  = m ? p1 : p0;
    const float4* repre = m ? r1 : r0;
    float4 va, vb;
    if (node < NU) {
        va = __ldg(pref + (size_t)li * 2);
        vb = __ldg(pref + (size_t)li * 2 + 1);
    } else {
        size_t o = (size_t)(li - NU * 8) * 2;
        va = __ldg(repre + o);
        vb = __ldg(repre + o + 1);
    }
    __half2 a = __floats2half2_rn(va.x, va.y);
    __half2 b = __floats2half2_rn(va.z, va.w);
    __half2 c = __floats2half2_rn(vb.x, vb.y);
    __half2 d = __floats2half2_rn(vb.z, vb.w);
    uint4 ov;
    ov.x = *reinterpret_cast<unsigned*>(&a);
    ov.y = *reinterpret_cast<unsigned*>(&b);
    ov.z = *reinterpret_cast<unsigned*>(&c);
    ov.w = *reinterpret_cast<unsigned*>(&d);
    (m ? h1 : h0)[li] = ov;
}

// ---------------------------------------------------------------------------
// CSC build (unchanged from the round-6 passing kernel)
// ---------------------------------------------------------------------------
__global__ void zero_deg_kernel(int* __restrict__ deg) {
    int i = blockIdx.x * blockDim.x + threadIdx.x;
    if (i < 2 * NN) deg[i] = 0;
}

__global__ void __launch_bounds__(256)
hist_kernel(const int* __restrict__ dst0, const int* __restrict__ dst1,
            int* __restrict__ deg, int* __restrict__ rank) {
    int b = blockIdx.x;
    int m = (b >= EDGE_BLOCKS) ? 1 : 0;
    int e = (b - m * EDGE_BLOCKS) * 256 + threadIdx.x;
    if (e >= NE) return;
    const int* dst = m ? dst1 : dst0;
    int d = __ldg(dst + e);
    rank[m * NE + e] = atomicAdd(deg + m * NN + d, 1);
}

__global__ void __launch_bounds__(SCAN_CHUNK)
scan1_kernel(const int* __restrict__ deg, int* __restrict__ off,
             int* __restrict__ partials) {
    __shared__ int sm[2][SCAN_CHUNK];
    int b = blockIdx.x;
    int m = (b >= N_CHUNKS) ? 1 : 0;
    int chunk = b - m * N_CHUNKS;
    int t = threadIdx.x;
    int li = chunk * SCAN_CHUNK + t;
    int v = (li < NN) ? deg[m * NN + li] : 0;
    sm[0][t] = v;
    __syncthreads();
    int cur = 0;
    #pragma unroll
    for (int ofs = 1; ofs < SCAN_CHUNK; ofs <<= 1) {
        int nxt = cur ^ 1;
        int val = sm[cur][t];
        if (t >= ofs) val += sm[cur][t - ofs];
        sm[nxt][t] = val;
        __syncthreads();
        cur = nxt;
    }
    int inclusive = sm[cur][t];
    if (li < NN) off[m * NN + li] = inclusive - v;
    if (t == SCAN_CHUNK - 1) partials[m * N_CHUNKS + chunk] = inclusive;
}

__global__ void __launch_bounds__(256)
scan2_kernel(const int* __restrict__ partials, int* __restrict__ scanned) {
    __shared__ int sm[2][256];
    int m = blockIdx.x;
    int t = threadIdx.x;
    int v = (t < N_CHUNKS) ? partials[m * N_CHUNKS + t] : 0;
    sm[0][t] = v;
    __syncthreads();
    int cur = 0;
    #pragma unroll
    for (int ofs = 1; ofs < 256; ofs <<= 1) {
        int nxt = cur ^ 1;
        int val = sm[cur][t];
        if (t >= ofs) val += sm[cur][t - ofs];
        sm[nxt][t] = val;
        __syncthreads();
        cur = nxt;
    }
    if (t < N_CHUNKS) scanned[m * N_CHUNKS + t] = sm[cur][t] - v;  // exclusive
}

__global__ void scan3_kernel(int* __restrict__ off,
                             const int* __restrict__ scanned) {
    int i = blockIdx.x * blockDim.x + threadIdx.x;
    if (i >= 2 * NN) return;
    int m = (i >= NN) ? 1 : 0;
    int li = i - m * NN;
    off[i] += scanned[m * N_CHUNKS + li / SCAN_CHUNK];
}

__global__ void __launch_bounds__(256)
sort_scatter_kernel(const int* __restrict__ src0, const int* __restrict__ dst0,
                    const float* __restrict__ w0,
                    const int* __restrict__ src1, const int* __restrict__ dst1,
                    const float* __restrict__ w1,
                    const int* __restrict__ off, const int* __restrict__ rank,
                    uint2* __restrict__ sw) {
    int b = blockIdx.x;
    int m = (b >= EDGE_BLOCKS) ? 1 : 0;
    int e = (b - m * EDGE_BLOCKS) * 256 + threadIdx.x;
    if (e >= NE) return;
    const int* src = m ? src1 : src0;
    const int* dst = m ? dst1 : dst0;
    const float* w = m ? w1 : w0;
    int d = __ldg(dst + e);
    int pos = __ldg(off + m * NN + d) + __ldg(rank + m * NE + e);
    sw[(size_t)m * NE + pos] =
        make_uint2((unsigned)__ldg(src + e), __float_as_uint(__ldg(w + e)));
}

// ---------------------------------------------------------------------------
// 8-lane pull kernel: lane j of 8 covers features [8j, 8j+8) = one uint4
// (16 B) of the 128 B fp16 row -> one LDG.128 per edge per lane. Halves
// per-edge LDG issue count vs the 16-lane/8 B version (R5/R6 showed the
// pulls are LSU-issue bound, not BW/latency bound). fp32 accumulation,
// batch-2 edge unroll.
//   TO_OUT: layer 3, writes fp32 d_out in concat layout (column m*64).
// ---------------------------------------------------------------------------
struct f8 { float4 a, b; };

__device__ __forceinline__ f8 unpack_h8(uint4 v) {
    __half2 h0 = *reinterpret_cast<__half2*>(&v.x);
    __half2 h1 = *reinterpret_cast<__half2*>(&v.y);
    __half2 h2 = *reinterpret_cast<__half2*>(&v.z);
    __half2 h3 = *reinterpret_cast<__half2*>(&v.w);
    float2 f0 = __half22float2(h0);
    float2 f1 = __half22float2(h1);
    float2 f2 = __half22float2(h2);
    float2 f3 = __half22float2(h3);
    f8 r;
    r.a = make_float4(f0.x, f0.y, f1.x, f1.y);
    r.b = make_float4(f2.x, f2.y, f3.x, f3.y);
    return r;
}

template<bool TO_OUT>
__global__ void __launch_bounds__(256)
pull8_kernel(const uint2* __restrict__ swBase,
             const int* __restrict__ offBase, const int* __restrict__ degBase,
             const uint4* __restrict__ hIn0, const uint4* __restrict__ hIn1,
             uint4* __restrict__ hOut0, uint4* __restrict__ hOut1,
             float* __restrict__ fout) {
    int b = blockIdx.x;
    int m = (b >= PULL8_BLOCKS) ? 1 : 0;
    int t = (b - m * PULL8_BLOCKS) * 256 + threadIdx.x;
    int node = t >> 3;
    int j = t & 7;
    if (node >= NN) return;

    const uint2* sw = swBase + (size_t)m * NE;
    const int* off = offBase + m * NN;
    const int* deg = degBase + m * NN;
    const uint4* hIn = m ? hIn1 : hIn0;

    // residual
    f8 acc = unpack_h8(__ldg(hIn + (size_t)node * 8 + j));
    acc.a.x *= DELTA; acc.a.y *= DELTA; acc.a.z *= DELTA; acc.a.w *= DELTA;
    acc.b.x *= DELTA; acc.b.y *= DELTA; acc.b.z *= DELTA; acc.b.w *= DELTA;
    f8 acc2;
    acc2.a = make_float4(0.f, 0.f, 0.f, 0.f);
    acc2.b = make_float4(0.f, 0.f, 0.f, 0.f);

    const int o = __ldg(off + node);
    const int n = __ldg(deg + node);
    const int end = o + n;

    int k = o;
    for (; k + 2 <= end; k += 2) {
        uint2 e0 = __ldg(sw + k);
        uint2 e1 = __ldg(sw + k + 1);
        f8 v0 = unpack_h8(__ldg(hIn + (size_t)e0.x * 8 + j));
        f8 v1 = unpack_h8(__ldg(hIn + (size_t)e1.x * 8 + j));
        float w0 = __uint_as_float(e0.y);
        float w1 = __uint_as_float(e1.y);
        acc.a.x  = fmaf(w0, v0.a.x, acc.a.x);
        acc.a.y  = fmaf(w0, v0.a.y, acc.a.y);
        acc.a.z  = fmaf(w0, v0.a.z, acc.a.z);
        acc.a.w  = fmaf(w0, v0.a.w, acc.a.w);
        acc.b.x  = fmaf(w0, v0.b.x, acc.b.x);
        acc.b.y  = fmaf(w0, v0.b.y, acc.b.y);
        acc.b.z  = fmaf(w0, v0.b.z, acc.b.z);
        acc.b.w  = fmaf(w0, v0.b.w, acc.b.w);
        acc2.a.x = fmaf(w1, v1.a.x, acc2.a.x);
        acc2.a.y = fmaf(w1, v1.a.y, acc2.a.y);
        acc2.a.z = fmaf(w1, v1.a.z, acc2.a.z);
        acc2.a.w = fmaf(w1, v1.a.w, acc2.a.w);
        acc2.b.x = fmaf(w1, v1.b.x, acc2.b.x);
        acc2.b.y = fmaf(w1, v1.b.y, acc2.b.y);
        acc2.b.z = fmaf(w1, v1.b.z, acc2.b.z);
        acc2.b.w = fmaf(w1, v1.b.w, acc2.b.w);
    }
    if (k < end) {
        uint2 e0 = __ldg(sw + k);
        f8 v0 = unpack_h8(__ldg(hIn + (size_t)e0.x * 8 + j));
        float w0 = __uint_as_float(e0.y);
        acc.a.x = fmaf(w0, v0.a.x, acc.a.x);
        acc.a.y = fmaf(w0, v0.a.y, acc.a.y);
        acc.a.z = fmaf(w0, v0.a.z, acc.a.z);
        acc.a.w = fmaf(w0, v0.a.w, acc.a.w);
        acc.b.x = fmaf(w0, v0.b.x, acc.b.x);
        acc.b.y = fmaf(w0, v0.b.y, acc.b.y);
        acc.b.z = fmaf(w0, v0.b.z, acc.b.z);
        acc.b.w = fmaf(w0, v0.b.w, acc.b.w);
    }
    acc.a.x += acc2.a.x; acc.a.y += acc2.a.y; acc.a.z += acc2.a.z; acc.a.w += acc2.a.w;
    acc.b.x += acc2.b.x; acc.b.y += acc2.b.y; acc.b.z += acc2.b.z; acc.b.w += acc2.b.w;

    if (TO_OUT) {
        int halfOff = m * 64;
        size_t base = (node < NU)
            ? (size_t)node * 128 + halfOff
            : (size_t)NU * 128 + (size_t)(node - NU) * 128 + halfOff;
        float4* p = reinterpret_cast<float4*>(fout + base + (size_t)j * 8);
        p[0] = acc.a;
        p[1] = acc.b;
    } else {
        uint4* hOut = m ? hOut1 : hOut0;
        __half2 ha = __floats2half2_rn(acc.a.x, acc.a.y);
        __half2 hb = __floats2half2_rn(acc.a.z, acc.a.w);
        __half2 hc = __floats2half2_rn(acc.b.x, acc.b.y);
        __half2 hd = __floats2half2_rn(acc.b.z, acc.b.w);
        uint4 ov;
        ov.x = *reinterpret_cast<unsigned*>(&ha);
        ov.y = *reinterpret_cast<unsigned*>(&hb);
        ov.z = *reinterpret_cast<unsigned*>(&hc);
        ov.w = *reinterpret_cast<unsigned*>(&hd);
        hOut[(size_t)node * 8 + j] = ov;
    }
}

// ---------------------------------------------------------------------------
// Orchestration: 10 launches total.
// ---------------------------------------------------------------------------
extern "C" void kernel_launch(void* const* d_in, const int* in_sizes, int n_in,
                              void* d_out, int out_size) {
    const int*   ei_img   = (const int*)  d_in[0];
    const float* ew_img   = (const float*)d_in[1];
    const int*   ei_txt   = (const int*)  d_in[2];
    const float* ew_txt   = (const float*)d_in[3];
    const float* img_pref = (const float*)d_in[4];
    const float* txt_pref = (const float*)d_in[5];
    const float* img_repr = (const float*)d_in[6];
    const float* txt_repr = (const float*)d_in[7];
    float* out = (float*)d_out;

    const int* src0 = ei_img;        const int* dst0 = ei_img + NE;
    const int* src1 = ei_txt;        const int* dst1 = ei_txt + NE;

    uint4 *hA, *hB;
    int *deg, *off, *rank, *partials, *scanned;
    uint2* sw;
    cudaGetSymbolAddress((void**)&hA, g_hA);
    cudaGetSymbolAddress((void**)&hB, g_hB);
    cudaGetSymbolAddress((void**)&deg, g_deg);
    cudaGetSymbolAddress((void**)&off, g_off);
    cudaGetSymbolAddress((void**)&rank, g_rank);
    cudaGetSymbolAddress((void**)&partials, g_partials);
    cudaGetSymbolAddress((void**)&scanned, g_scanned);
    cudaGetSymbolAddress((void**)&sw, g_sw);

    uint4* hA0 = hA;
    uint4* hA1 = hA + (size_t)NN * 8;
    uint4* hB0 = hB;
    uint4* hB1 = hB + (size_t)NN * 8;

    // Convert inputs to fp16 ego buffers (hA)
    convert_kernel<<<CVT_BLOCKS, 256>>>(
        reinterpret_cast<const float4*>(img_pref),
        reinterpret_cast<const float4*>(img_repr),
        reinterpret_cast<const float4*>(txt_pref),
        reinterpret_cast<const float4*>(txt_repr),
        hA0, hA1);

    // Build both CSCs
    zero_deg_kernel<<<NODE2_BLOCKS, 256>>>(deg);
    hist_kernel<<<2 * EDGE_BLOCKS, 256>>>(dst0, dst1, deg, rank);
    scan1_kernel<<<2 * N_CHUNKS, SCAN_CHUNK>>>(deg, off, partials);
    scan2_kernel<<<2, 256>>>(partials, scanned);
    scan3_kernel<<<NODE2_BLOCKS, 256>>>(off, scanned);
    sort_scatter_kernel<<<2 * EDGE_BLOCKS, 256>>>(
        src0, dst0, ew_img, src1, dst1, ew_txt, off, rank, sw);

    // Layer 1: hA -> hB
    pull8_kernel<false><<<2 * PULL8_BLOCKS, 256>>>(
        sw, off, deg, hA0, hA1, hB0, hB1, nullptr);
    // Layer 2: hB -> hA
    pull8_kernel<false><<<2 * PULL8_BLOCKS, 256>>>(
        sw, off, deg, hB0, hB1, hA0, hA1, nullptr);
    // Layer 3: hA -> d_out (fp32 concat layout)
    pull8_kernel<true><<<2 * PULL8_BLOCKS, 256>>>(
        sw, off, deg, hA0, hA1, nullptr, nullptr, out);
}